// round 2
// baseline (speedup 1.0000x reference)
#include <cuda_runtime.h>

// Problem shape (fixed by setup_inputs): B=8, S1=2048, S2=2048, D=1024
#define BATCH 8
#define SEQ1  2048
#define SEQ2  2048
#define DIM   1024
#define MASK_FILL_V (-100.0f)

// Scratch (no cudaMalloc allowed): out1 [B,S1,D] and scoresT [B,S2,S1]
__device__ float g_out1[(size_t)BATCH * SEQ1 * DIM];        // 67 MB
__device__ float g_scores[(size_t)BATCH * SEQ2 * SEQ1];     // 134 MB

// ---------------------------------------------------------------------------
// Generic 128x128x16 fp32 SIMT GEMM.
//   NT=true : C[M,N] = A[M,K] * B[N,K]^T     (both K-contiguous)
//   NT=false: C[M,N] = A[M,K] * B[K,N]       (A K-contig, B N-contig)
// Optional epilogue mask over the N (column) dimension: mask is a 4-byte-per-
// element array (int32 or float32 encoding of bool); word==0 means masked ->
// write MASK_FILL instead of the accumulator.
// All dims are multiples of the tile sizes for this problem -> no bounds checks.
// ---------------------------------------------------------------------------
template<bool NT, bool MASKED>
__global__ __launch_bounds__(256, 2)
void gemm128(const float* __restrict__ Ag, const float* __restrict__ Bg,
             float* __restrict__ Cg, const unsigned int* __restrict__ maskg,
             int M, int N, int K,
             size_t sA, size_t sB, size_t sC, size_t sMask)
{
    constexpr int BM = 128, BN = 128, BK = 16;
    __shared__ float As[BK][BM];
    __shared__ float Bs[BK][BN];

    const int tid = threadIdx.x;
    const int tx = tid & 15;        // column group
    const int ty = tid >> 4;        // row group
    const int bz = blockIdx.z;

    const float* A = Ag + (size_t)bz * sA;
    const float* B = Bg + (size_t)bz * sB;
    float*       C = Cg + (size_t)bz * sC;

    const int m0 = blockIdx.y * BM;
    const int n0 = blockIdx.x * BN;

    float acc[8][8];
#pragma unroll
    for (int i = 0; i < 8; i++)
#pragma unroll
        for (int j = 0; j < 8; j++) acc[i][j] = 0.0f;

    for (int kk = 0; kk < K; kk += BK) {
        // --- A tile: [BM x BK], K-contiguous -> transpose into As[k][m]
#pragma unroll
        for (int it = 0; it < 2; it++) {
            int idx = it * 256 + tid;       // 0..511 float4s
            int r   = idx >> 2;             // 0..127 (row within tile)
            int c4  = idx & 3;              // 0..3   (float4 within the 16 K)
            float4 v = *(const float4*)(A + (size_t)(m0 + r) * K + kk + c4 * 4);
            As[c4 * 4 + 0][r] = v.x;
            As[c4 * 4 + 1][r] = v.y;
            As[c4 * 4 + 2][r] = v.z;
            As[c4 * 4 + 3][r] = v.w;
        }
        // --- B tile
        if (NT) {
            // B is [N,K] K-contiguous -> transpose into Bs[k][n]
#pragma unroll
            for (int it = 0; it < 2; it++) {
                int idx = it * 256 + tid;
                int r   = idx >> 2;
                int c4  = idx & 3;
                float4 v = *(const float4*)(B + (size_t)(n0 + r) * K + kk + c4 * 4);
                Bs[c4 * 4 + 0][r] = v.x;
                Bs[c4 * 4 + 1][r] = v.y;
                Bs[c4 * 4 + 2][r] = v.z;
                Bs[c4 * 4 + 3][r] = v.w;
            }
        } else {
            // B is [K,N] N-contiguous -> direct copy into Bs[k][n]
#pragma unroll
            for (int it = 0; it < 2; it++) {
                int idx = it * 256 + tid;   // 0..511 float4s
                int r   = idx >> 5;         // 0..15 (k within tile)
                int c4  = idx & 31;         // 0..31 (float4 within 128 n)
                *(float4*)&Bs[r][c4 * 4] =
                    *(const float4*)(B + (size_t)(kk + r) * N + n0 + c4 * 4);
            }
        }
        __syncthreads();

#pragma unroll
        for (int k = 0; k < BK; k++) {
            float a[8], b[8];
            *(float4*)&a[0] = *(const float4*)&As[k][ty * 8];
            *(float4*)&a[4] = *(const float4*)&As[k][ty * 8 + 4];
            *(float4*)&b[0] = *(const float4*)&Bs[k][tx * 8];
            *(float4*)&b[4] = *(const float4*)&Bs[k][tx * 8 + 4];
#pragma unroll
            for (int i = 0; i < 8; i++)
#pragma unroll
                for (int j = 0; j < 8; j++)
                    acc[i][j] = fmaf(a[i], b[j], acc[i][j]);
        }
        __syncthreads();
    }

    // --- epilogue (optional column mask, 4-byte word per element) ---
    bool mok[8];
    if (MASKED) {
        const unsigned int* mk = maskg + (size_t)bz * sMask + n0 + tx * 8;
#pragma unroll
        for (int j = 0; j < 8; j++) mok[j] = (mk[j] != 0u);
    }
#pragma unroll
    for (int i = 0; i < 8; i++) {
        int m = m0 + ty * 8 + i;
        float* crow = C + (size_t)m * N + n0 + tx * 8;
#pragma unroll
        for (int j = 0; j < 8; j += 4) {
            float4 v = make_float4(acc[i][j], acc[i][j + 1],
                                   acc[i][j + 2], acc[i][j + 3]);
            if (MASKED) {
                if (!mok[j])     v.x = MASK_FILL_V;
                if (!mok[j + 1]) v.y = MASK_FILL_V;
                if (!mok[j + 2]) v.z = MASK_FILL_V;
                if (!mok[j + 3]) v.w = MASK_FILL_V;
            }
            *(float4*)(crow + j) = v;
        }
    }
}

// ---------------------------------------------------------------------------
// Row softmax over contiguous length-2048 rows of g_scores ([b,t,s] layout).
// One block (256 threads) per row; values held in registers (8 per thread).
// Note: an all-masked row (all -100) reduces to uniform weights, matching the
// reference softmax exactly.
// ---------------------------------------------------------------------------
__global__ __launch_bounds__(256)
void softmax_rows(float* __restrict__ scores)
{
    const int tid = threadIdx.x;
    float* row = scores + (size_t)blockIdx.x * SEQ1;

    float v[8];
    float mx = -3.4e38f;
#pragma unroll
    for (int i = 0; i < 8; i++) {
        v[i] = row[tid + (i << 8)];
        mx = fmaxf(mx, v[i]);
    }
#pragma unroll
    for (int o = 16; o > 0; o >>= 1)
        mx = fmaxf(mx, __shfl_xor_sync(0xffffffffu, mx, o));

    __shared__ float smax[8];
    __shared__ float ssum[8];
    if ((tid & 31) == 0) smax[tid >> 5] = mx;
    __syncthreads();
    mx = smax[0];
#pragma unroll
    for (int w = 1; w < 8; w++) mx = fmaxf(mx, smax[w]);

    float s = 0.0f;
#pragma unroll
    for (int i = 0; i < 8; i++) {
        v[i] = __expf(v[i] - mx);
        s += v[i];
    }
#pragma unroll
    for (int o = 16; o > 0; o >>= 1)
        s += __shfl_xor_sync(0xffffffffu, s, o);
    if ((tid & 31) == 0) ssum[tid >> 5] = s;
    __syncthreads();
    s = ssum[0];
#pragma unroll
    for (int w = 1; w < 8; w++) s += ssum[w];

    const float inv = 1.0f / s;
#pragma unroll
    for (int i = 0; i < 8; i++)
        row[tid + (i << 8)] = v[i] * inv;
}

// ---------------------------------------------------------------------------
extern "C" void kernel_launch(void* const* d_in, const int* in_sizes, int n_in,
                              void* d_out, int out_size)
{
    const float*        input1 = (const float*)d_in[0];          // [B,S1,D]
    const float*        input2 = (const float*)d_in[1];          // [B,S2,D]
    const unsigned int* mask   = (const unsigned int*)d_in[2];   // [B,S1] as 4-byte words
    const float*        weight = (const float*)d_in[3];          // [D,D]
    float*              out    = (float*)d_out;                  // [B,S2,D]

    float *out1p = nullptr, *scoresp = nullptr;
    cudaGetSymbolAddress((void**)&out1p, g_out1);
    cudaGetSymbolAddress((void**)&scoresp, g_scores);

    dim3 blk(256);

    // 1) out1 = input1 @ weight^T   (NT, no batch)
    gemm128<true, false><<<dim3(DIM / 128, (BATCH * SEQ1) / 128, 1), blk>>>(
        input1, weight, out1p, nullptr,
        BATCH * SEQ1, DIM, DIM, 0, 0, 0, 0);

    // 2) scoresT[b,t,s] = input2[b,t,:] . out1[b,s,:]  (batched NT, mask on s)
    gemm128<true, true><<<dim3(SEQ1 / 128, SEQ2 / 128, BATCH), blk>>>(
        input2, out1p, scoresp, mask,
        SEQ2, SEQ1, DIM,
        (size_t)SEQ2 * DIM, (size_t)SEQ1 * DIM, (size_t)SEQ2 * SEQ1,
        (size_t)SEQ1);

    // 3) softmax over s (contiguous rows of scoresT)
    softmax_rows<<<BATCH * SEQ2, 256>>>(scoresp);

    // 4) out[b,t,d] = sum_s P[b,t,s] * input1[b,s,d]   (batched NN)
    gemm128<false, false><<<dim3(DIM / 128, SEQ2 / 128, BATCH), blk>>>(
        scoresp, input1, out, nullptr,
        SEQ2, DIM, SEQ1,
        (size_t)SEQ2 * SEQ1, (size_t)SEQ1 * DIM, (size_t)SEQ2 * DIM, 0);
}

// round 3
// speedup vs baseline: 2.1612x; 2.1612x over previous
#include <cuda_runtime.h>
#include <cuda_bf16.h>
#include <stdint.h>

#define BATCH 8
#define SEQ1  2048
#define SEQ2  2048
#define DIM   1024
#define MASK_FILL_V (-100.0f)

using bf16 = __nv_bfloat16;

// ---------------- scratch (static __device__, no allocation) ----------------
__device__ bf16  g_in1h[(size_t)BATCH*SEQ1*DIM];
__device__ bf16  g_in1l[(size_t)BATCH*SEQ1*DIM];
__device__ bf16  g_in2h[(size_t)BATCH*SEQ2*DIM];
__device__ bf16  g_in2l[(size_t)BATCH*SEQ2*DIM];
__device__ bf16  g_wh[(size_t)DIM*DIM];
__device__ bf16  g_wl[(size_t)DIM*DIM];
__device__ bf16  g_o1h[(size_t)BATCH*SEQ1*DIM];
__device__ bf16  g_o1l[(size_t)BATCH*SEQ1*DIM];
__device__ float g_scores[(size_t)BATCH*SEQ2*SEQ1];
__device__ bf16  g_ph[(size_t)BATCH*SEQ2*SEQ1];
__device__ bf16  g_pl[(size_t)BATCH*SEQ2*SEQ1];

__device__ __forceinline__ void split2(float x, bf16 &h, bf16 &l) {
    h = __float2bfloat16(x);
    l = __float2bfloat16(x - __bfloat162float(h));
}

// ---------------- fp32 -> (hi, lo) bf16 split ----------------
__global__ __launch_bounds__(256) void split_kernel(const float* __restrict__ x,
                                                    bf16* __restrict__ h,
                                                    bf16* __restrict__ l) {
    size_t i = ((size_t)blockIdx.x * 256 + threadIdx.x) * 4;
    float4 v = *(const float4*)(x + i);
    bf16 h0,h1,h2,h3,l0,l1,l2,l3;
    split2(v.x,h0,l0); split2(v.y,h1,l1); split2(v.z,h2,l2); split2(v.w,h3,l3);
    __nv_bfloat162 a, b;
    a.x=h0; a.y=h1; b.x=h2; b.y=h3;
    ((__nv_bfloat162*)(h+i))[0] = a; ((__nv_bfloat162*)(h+i))[1] = b;
    a.x=l0; a.y=l1; b.x=l2; b.y=l3;
    ((__nv_bfloat162*)(l+i))[0] = a; ((__nv_bfloat162*)(l+i))[1] = b;
}

// ---------------- async copy / mma helpers ----------------
#define CP16(dst, src) asm volatile("cp.async.cg.shared.global [%0], [%1], 16;\n" :: "r"(dst), "l"(src))
#define CP_COMMIT()    asm volatile("cp.async.commit_group;\n")
#define CP_WAIT1()     asm volatile("cp.async.wait_group 1;\n")
#define CP_WAIT0()     asm volatile("cp.async.wait_group 0;\n")

#define MMA_BF16(d, a, b) asm volatile( \
  "mma.sync.aligned.m16n8k16.row.col.f32.bf16.bf16.f32 " \
  "{%0,%1,%2,%3},{%4,%5,%6,%7},{%8,%9},{%0,%1,%2,%3};\n" \
  : "+f"(d[0]), "+f"(d[1]), "+f"(d[2]), "+f"(d[3]) \
  : "r"(a[0]), "r"(a[1]), "r"(a[2]), "r"(a[3]), "r"(b[0]), "r"(b[1]))

__device__ __forceinline__ uint32_t pk16(const bf16* p0, const bf16* p1) {
    uint16_t u0 = *(const uint16_t*)p0, u1 = *(const uint16_t*)p1;
    return (uint32_t)u0 | ((uint32_t)u1 << 16);
}

// ---------------------------------------------------------------------------
// Split-bf16 tensor-core GEMM, 128x128 tile, BK=16, 256 threads (8 warps,
// warp tile 64x32). 3-product scheme: C += Ahi*Bhi + Ahi*Blo + Alo*Bhi.
//   NN=0: B stored [N][K] K-contig (NT GEMM).   NN=1: B stored [K][N] N-contig.
//   EPI=0: fp32 out.  EPI=1: fp32 out + column mask (4-byte bool words).
//   EPI=2: out written as (hi, lo) bf16 pair arrays.
// smem: A tiles padded to stride 24 halves, NN B tiles stride 136 halves;
// fragment loads verified conflict-free.
// ---------------------------------------------------------------------------
template<int NN, int EPI>
__global__ __launch_bounds__(256, 2)
void gemm_mma(const bf16* __restrict__ Ahg, const bf16* __restrict__ Alg,
              const bf16* __restrict__ Bhg, const bf16* __restrict__ Blg,
              float* __restrict__ Cfg, bf16* __restrict__ Chg, bf16* __restrict__ Clg,
              const unsigned int* __restrict__ maskg,
              int M, int N, int K,
              size_t sA, size_t sB, size_t sC, size_t sMask)
{
    // [stage][A=0/B=1][hi=0/lo=1][3072 halves]  = 49152 bytes
    __shared__ __align__(16) bf16 sm[2][2][2][3072];

    const int tid  = threadIdx.x;
    const int warp = tid >> 5, lane = tid & 31;
    const int wm = warp >> 2, wn = warp & 3;     // 2 x 4 warp grid
    const int g  = lane >> 2, tq = lane & 3;
    const int bz = blockIdx.z;
    const int m0 = blockIdx.y * 128, n0 = blockIdx.x * 128;

    const bf16* Ah = Ahg + (size_t)bz * sA;
    const bf16* Al = Alg + (size_t)bz * sA;
    const bf16* Bh = Bhg + (size_t)bz * sB;
    const bf16* Bl = Blg + (size_t)bz * sB;

    // gmem chunk for this thread (16 bytes = 8 halves per array per stage)
    const int ar = tid >> 1, ah8 = (tid & 1) * 8;
    const bf16* gAh = Ah + (size_t)(m0 + ar) * K + ah8;
    const bf16* gAl = Al + (size_t)(m0 + ar) * K + ah8;
    const int offA = ar * 24 + ah8;              // smem halves

    const bf16 *gBh, *gBl;  int offB;
    if (NN) {
        const int bk = tid >> 4, bn = (tid & 15) * 8;
        gBh = Bh + (size_t)bk * N + n0 + bn;
        gBl = Bl + (size_t)bk * N + n0 + bn;
        offB = bk * 136 + bn;
    } else {
        gBh = Bh + (size_t)(n0 + ar) * K + ah8;
        gBl = Bl + (size_t)(n0 + ar) * K + ah8;
        offB = offA;
    }

    const uint32_t smb = (uint32_t)__cvta_generic_to_shared(&sm[0][0][0][0]);

    float acc[4][4][4];
#pragma unroll
    for (int mt = 0; mt < 4; mt++)
#pragma unroll
        for (int nt = 0; nt < 4; nt++)
#pragma unroll
            for (int c = 0; c < 4; c++) acc[mt][nt][c] = 0.0f;

    const int NK = K / 16;

    // --- issue stage st covering k offset kk ---
#define ISSUE(st, kk) do { \
        uint32_t b_ = smb + (st) * 24576u; \
        size_t kA_ = (size_t)(kk); \
        size_t kB_ = NN ? (size_t)(kk) * N : (size_t)(kk); \
        CP16(b_ +     0u + offA * 2, gAh + kA_); \
        CP16(b_ +  6144u + offA * 2, gAl + kA_); \
        CP16(b_ + 12288u + offB * 2, gBh + kB_); \
        CP16(b_ + 18432u + offB * 2, gBl + kB_); \
        CP_COMMIT(); \
    } while (0)

    ISSUE(0, 0);

    int st = 0;
    for (int ki = 0; ki < NK; ki++) {
        const bool more = (ki + 1) < NK;
        if (more) ISSUE(st ^ 1, (ki + 1) * 16);
        if (more) { CP_WAIT1(); } else { CP_WAIT0(); }
        __syncthreads();

        const bf16* As_h = sm[st][0][0];
        const bf16* As_l = sm[st][0][1];
        const bf16* Bs_h = sm[st][1][0];
        const bf16* Bs_l = sm[st][1][1];

        uint32_t bh[4][2], bl[4][2];
#pragma unroll
        for (int nt = 0; nt < 4; nt++) {
            const int col = wn * 32 + nt * 8 + g;
            if (!NN) {
                const int b0 = col * 24 + tq * 2;
                bh[nt][0] = *(const uint32_t*)(Bs_h + b0);
                bh[nt][1] = *(const uint32_t*)(Bs_h + b0 + 8);
                bl[nt][0] = *(const uint32_t*)(Bs_l + b0);
                bl[nt][1] = *(const uint32_t*)(Bs_l + b0 + 8);
            } else {
                const int r0 = tq * 2;
                bh[nt][0] = pk16(Bs_h + r0*136 + col,     Bs_h + (r0+1)*136 + col);
                bh[nt][1] = pk16(Bs_h + (r0+8)*136 + col, Bs_h + (r0+9)*136 + col);
                bl[nt][0] = pk16(Bs_l + r0*136 + col,     Bs_l + (r0+1)*136 + col);
                bl[nt][1] = pk16(Bs_l + (r0+8)*136 + col, Bs_l + (r0+9)*136 + col);
            }
        }
#pragma unroll
        for (int mt = 0; mt < 4; mt++) {
            const int row = wm * 64 + mt * 16 + g;
            const int a0 = row * 24 + tq * 2;
            uint32_t ah[4], al[4];
            ah[0] = *(const uint32_t*)(As_h + a0);
            ah[1] = *(const uint32_t*)(As_h + a0 + 8*24);
            ah[2] = *(const uint32_t*)(As_h + a0 + 8);
            ah[3] = *(const uint32_t*)(As_h + a0 + 8*24 + 8);
            al[0] = *(const uint32_t*)(As_l + a0);
            al[1] = *(const uint32_t*)(As_l + a0 + 8*24);
            al[2] = *(const uint32_t*)(As_l + a0 + 8);
            al[3] = *(const uint32_t*)(As_l + a0 + 8*24 + 8);
#pragma unroll
            for (int nt = 0; nt < 4; nt++) {
                MMA_BF16(acc[mt][nt], ah, bh[nt]);
                MMA_BF16(acc[mt][nt], ah, bl[nt]);
                MMA_BF16(acc[mt][nt], al, bh[nt]);
            }
        }
        __syncthreads();
        st ^= 1;
    }
#undef ISSUE

    // ---------------- epilogue ----------------
    unsigned mok0[4], mok1[4];
    if (EPI == 1) {
        const unsigned int* mk = maskg + (size_t)bz * sMask;
#pragma unroll
        for (int nt = 0; nt < 4; nt++) {
            const int col = n0 + wn * 32 + nt * 8 + tq * 2;
            mok0[nt] = mk[col];
            mok1[nt] = mk[col + 1];
        }
    }
    float* Cf = (EPI <= 1) ? Cfg + (size_t)bz * sC : nullptr;
    bf16*  Ch = (EPI == 2) ? Chg + (size_t)bz * sC : nullptr;
    bf16*  Cl = (EPI == 2) ? Clg + (size_t)bz * sC : nullptr;

#pragma unroll
    for (int mt = 0; mt < 4; mt++) {
        const int r0 = m0 + wm * 64 + mt * 16 + g;
#pragma unroll
        for (int nt = 0; nt < 4; nt++) {
            const int col = n0 + wn * 32 + nt * 8 + tq * 2;
            float c0 = acc[mt][nt][0], c1 = acc[mt][nt][1];
            float c2 = acc[mt][nt][2], c3 = acc[mt][nt][3];
            if (EPI == 1) {
                if (!mok0[nt]) { c0 = MASK_FILL_V; c2 = MASK_FILL_V; }
                if (!mok1[nt]) { c1 = MASK_FILL_V; c3 = MASK_FILL_V; }
            }
            if (EPI <= 1) {
                float2 v0 = make_float2(c0, c1), v1 = make_float2(c2, c3);
                *(float2*)(Cf + (size_t)r0 * N + col)       = v0;
                *(float2*)(Cf + (size_t)(r0 + 8) * N + col) = v1;
            } else {
                bf16 h0,h1,h2,h3,l0,l1,l2,l3;
                split2(c0,h0,l0); split2(c1,h1,l1); split2(c2,h2,l2); split2(c3,h3,l3);
                __nv_bfloat162 t;
                t.x=h0; t.y=h1; *(__nv_bfloat162*)(Ch + (size_t)r0*N + col)     = t;
                t.x=h2; t.y=h3; *(__nv_bfloat162*)(Ch + (size_t)(r0+8)*N + col) = t;
                t.x=l0; t.y=l1; *(__nv_bfloat162*)(Cl + (size_t)r0*N + col)     = t;
                t.x=l2; t.y=l3; *(__nv_bfloat162*)(Cl + (size_t)(r0+8)*N + col) = t;
            }
        }
    }
}

// ---------------------------------------------------------------------------
// Row softmax over contiguous length-2048 rows of scores [b,t,s]; writes the
// probabilities as (hi, lo) bf16 split for the final tensor-core GEMM.
// ---------------------------------------------------------------------------
__global__ __launch_bounds__(256)
void softmax_rows(const float* __restrict__ scores,
                  bf16* __restrict__ ph, bf16* __restrict__ pl)
{
    const int tid = threadIdx.x;
    const size_t base = (size_t)blockIdx.x * SEQ1;
    const float* row = scores + base;

    float v[8];
    float mx = -3.4e38f;
#pragma unroll
    for (int i = 0; i < 8; i++) {
        v[i] = row[tid + (i << 8)];
        mx = fmaxf(mx, v[i]);
    }
#pragma unroll
    for (int o = 16; o > 0; o >>= 1)
        mx = fmaxf(mx, __shfl_xor_sync(0xffffffffu, mx, o));

    __shared__ float smax[8];
    __shared__ float ssum[8];
    if ((tid & 31) == 0) smax[tid >> 5] = mx;
    __syncthreads();
    mx = smax[0];
#pragma unroll
    for (int w = 1; w < 8; w++) mx = fmaxf(mx, smax[w]);

    float s = 0.0f;
#pragma unroll
    for (int i = 0; i < 8; i++) {
        v[i] = __expf(v[i] - mx);
        s += v[i];
    }
#pragma unroll
    for (int o = 16; o > 0; o >>= 1)
        s += __shfl_xor_sync(0xffffffffu, s, o);
    if ((tid & 31) == 0) ssum[tid >> 5] = s;
    __syncthreads();
    s = ssum[0];
#pragma unroll
    for (int w = 1; w < 8; w++) s += ssum[w];

    const float inv = 1.0f / s;
#pragma unroll
    for (int i = 0; i < 8; i++) {
        const float p = v[i] * inv;
        const size_t idx = base + tid + (i << 8);
        bf16 h, l; split2(p, h, l);
        ph[idx] = h; pl[idx] = l;
    }
}

// ---------------------------------------------------------------------------
extern "C" void kernel_launch(void* const* d_in, const int* in_sizes, int n_in,
                              void* d_out, int out_size)
{
    const float*        input1 = (const float*)d_in[0];          // [B,S1,D]
    const float*        input2 = (const float*)d_in[1];          // [B,S2,D]
    const unsigned int* mask   = (const unsigned int*)d_in[2];   // [B,S1] 4-byte words
    const float*        weight = (const float*)d_in[3];          // [D,D]
    float*              out    = (float*)d_out;                  // [B,S2,D]

    bf16 *in1h, *in1l, *in2h, *in2l, *wh, *wl, *o1h, *o1l, *ph, *pl;
    float *scoresp;
    cudaGetSymbolAddress((void**)&in1h, g_in1h);
    cudaGetSymbolAddress((void**)&in1l, g_in1l);
    cudaGetSymbolAddress((void**)&in2h, g_in2h);
    cudaGetSymbolAddress((void**)&in2l, g_in2l);
    cudaGetSymbolAddress((void**)&wh,  g_wh);
    cudaGetSymbolAddress((void**)&wl,  g_wl);
    cudaGetSymbolAddress((void**)&o1h, g_o1h);
    cudaGetSymbolAddress((void**)&o1l, g_o1l);
    cudaGetSymbolAddress((void**)&ph,  g_ph);
    cudaGetSymbolAddress((void**)&pl,  g_pl);
    cudaGetSymbolAddress((void**)&scoresp, g_scores);

    const size_t n1 = (size_t)BATCH * SEQ1 * DIM;

    // 0) split inputs into (hi, lo) bf16
    split_kernel<<<(unsigned)(n1 / 1024), 256>>>(input1, in1h, in1l);
    split_kernel<<<(unsigned)(n1 / 1024), 256>>>(input2, in2h, in2l);
    split_kernel<<<(unsigned)((size_t)DIM * DIM / 1024), 256>>>(weight, wh, wl);

    // 1) out1 = input1 @ weight^T   (NT, split-bf16 out)
    gemm_mma<0, 2><<<dim3(DIM / 128, (BATCH * SEQ1) / 128, 1), 256>>>(
        in1h, in1l, wh, wl, nullptr, o1h, o1l, nullptr,
        BATCH * SEQ1, DIM, DIM, 0, 0, 0, 0);

    // 2) scoresT[b,t,s] = input2[b,t,:] . out1[b,s,:]  (batched NT, mask on s)
    gemm_mma<0, 1><<<dim3(SEQ1 / 128, SEQ2 / 128, BATCH), 256>>>(
        in2h, in2l, o1h, o1l, scoresp, nullptr, nullptr, mask,
        SEQ2, SEQ1, DIM,
        (size_t)SEQ2 * DIM, (size_t)SEQ1 * DIM, (size_t)SEQ2 * SEQ1, (size_t)SEQ1);

    // 3) softmax over s + split probabilities
    softmax_rows<<<BATCH * SEQ2, 256>>>(scoresp, ph, pl);

    // 4) out[b,t,d] = sum_s P[b,t,s] * input1[b,s,d]   (batched NN, fp32 out)
    gemm_mma<1, 0><<<dim3(DIM / 128, SEQ2 / 128, BATCH), 256>>>(
        ph, pl, in1h, in1l, out, nullptr, nullptr, nullptr,
        SEQ2, DIM, SEQ1,
        (size_t)SEQ2 * SEQ1, (size_t)SEQ1 * DIM, (size_t)SEQ2 * DIM, 0);
}